// round 5
// baseline (speedup 1.0000x reference)
#include <cuda_runtime.h>
#include <cuda_bf16.h>

#define DIM 64
#define N_LAYERS 3
#define NODES_MAX 262144
#define EDGES_MAX 16000000

// -------- static device scratch (no allocations allowed) --------
// NOTE: these symbols are referenced ONLY from device code. Passing them as
// kernel arguments from host code yields the host shadow address (which ATS
// happily dereferences on GB300) — that was the R2-R4 bug.
__device__ int   g_is64;                        // 1 if index inputs are int64
__device__ int   g_counts [NODES_MAX];
__device__ int   g_offsets[NODES_MAX + 1];
__device__ int   g_cursor [NODES_MAX];
__device__ int2  g_csr    [EDGES_MAX];          // (src, val-bits) grouped by dst
__device__ float g_bufA   [NODES_MAX * DIM];
__device__ float g_bufB   [NODES_MAX * DIM];
__device__ float g_acc    [NODES_MAX * DIM];

// -------- index load helper: int32 or int64 input buffers --------
__device__ __forceinline__ int load_idx(const void* p, int i, bool is64) {
    if (is64) return (int)((const long long*)p)[i];
    return ((const int*)p)[i];
}

// -------- dtype detection: odd 32-bit words all zero => int64 --------
__global__ void detect_kernel(const unsigned int* __restrict__ p, int nslots) {
    __shared__ unsigned int acc;
    if (threadIdx.x == 0) acc = 0u;
    __syncthreads();
    unsigned int v = 0u;
    for (int s = threadIdx.x; s < nslots; s += 1024) v |= p[2 * s + 1];
    if (v) atomicOr(&acc, 1u);
    __syncthreads();
    if (threadIdx.x == 0) g_is64 = (acc == 0u) ? 1 : 0;
}

// -------- init: cur0 = concat(user_emb, item_emb); acc = cur0; counts = 0 ----
__global__ void init_kernel(const float* __restrict__ ue, const float* __restrict__ ie,
                            int nU4, int nT4, int n_nodes) {
    int i = blockIdx.x * blockDim.x + threadIdx.x;   // float4 index
    if (i < nT4) {
        float4 v = (i < nU4) ? ((const float4*)ue)[i] : ((const float4*)ie)[i - nU4];
        ((float4*)g_bufA)[i] = v;
        ((float4*)g_acc)[i]  = v;
    }
    if (i < n_nodes) g_counts[i] = 0;
}

// -------- histogram of destinations --------
__global__ void hist_kernel(const void* __restrict__ dst, int n_edges) {
    const bool is64 = (g_is64 != 0);
    int stride = gridDim.x * blockDim.x;
    for (int e = blockIdx.x * blockDim.x + threadIdx.x; e < n_edges; e += stride)
        atomicAdd(&g_counts[load_idx(dst, e, is64)], 1);
}

// -------- single-block exclusive scan: counts -> offsets, cursor --------
__global__ void scan_kernel(int n_nodes) {
    __shared__ int sh[1024];
    __shared__ int carry;
    if (threadIdx.x == 0) carry = 0;
    __syncthreads();
    for (int base = 0; base < n_nodes; base += 1024) {
        int i = base + threadIdx.x;
        int v = (i < n_nodes) ? g_counts[i] : 0;
        sh[threadIdx.x] = v;
        __syncthreads();
        for (int off = 1; off < 1024; off <<= 1) {
            int t = (threadIdx.x >= off) ? sh[threadIdx.x - off] : 0;
            __syncthreads();
            sh[threadIdx.x] += t;
            __syncthreads();
        }
        int incl = sh[threadIdx.x];
        int excl = incl - v;
        if (i < n_nodes) {
            g_offsets[i] = carry + excl;
            g_cursor [i] = carry + excl;
        }
        __syncthreads();
        if (threadIdx.x == 1023) carry += sh[1023];
        __syncthreads();
    }
    if (threadIdx.x == 0) g_offsets[n_nodes] = carry;   // == n_edges
}

// -------- scatter edges into CSR slots --------
__global__ void fill_kernel(const void* __restrict__ src, const void* __restrict__ dst,
                            const float* __restrict__ val, int n_edges) {
    const bool is64 = (g_is64 != 0);
    int stride = gridDim.x * blockDim.x;
    for (int e = blockIdx.x * blockDim.x + threadIdx.x; e < n_edges; e += stride) {
        int d = load_idx(dst, e, is64);
        int pos = atomicAdd(&g_cursor[d], 1);
        g_csr[pos] = make_int2(load_idx(src, e, is64), __float_as_int(val[e]));
    }
}

// -------- SpMM gather: one warp per dst node; lane owns a float2 of the row --
// sel=0: x=g_bufA, y=g_bufB.  sel=1: x=g_bufB, y=g_bufA.
// Buffers resolved in DEVICE code so symbol addresses are correct.
__global__ void __launch_bounds__(256)
spmm_kernel(int sel, int n_nodes) {
    const float* __restrict__ x = sel ? g_bufB : g_bufA;
    float*       __restrict__ y = sel ? g_bufA : g_bufB;
    int warp = (blockIdx.x * blockDim.x + threadIdx.x) >> 5;
    int lane = threadIdx.x & 31;
    if (warp >= n_nodes) return;
    int beg = g_offsets[warp];
    int end = g_offsets[warp + 1];

    float2 s = make_float2(0.f, 0.f);
    int e = beg;
    for (; e + 32 <= end; e += 32) {
        int2 ev = g_csr[e + lane];
        #pragma unroll
        for (int k = 0; k < 32; k++) {
            int   sN = __shfl_sync(0xffffffffu, ev.x, k);
            float vN = __int_as_float(__shfl_sync(0xffffffffu, ev.y, k));
            float2 xf = *(const float2*)(x + (size_t)sN * DIM + lane * 2);
            s.x += vN * xf.x;
            s.y += vN * xf.y;
        }
    }
    int n = end - e;
    if (n > 0) {
        int2 ev = (lane < n) ? g_csr[e + lane] : make_int2(0, 0);
        for (int k = 0; k < n; k++) {
            int   sN = __shfl_sync(0xffffffffu, ev.x, k);
            float vN = __int_as_float(__shfl_sync(0xffffffffu, ev.y, k));
            float2 xf = *(const float2*)(x + (size_t)sN * DIM + lane * 2);
            s.x += vN * xf.x;
            s.y += vN * xf.y;
        }
    }

    ((float2*)(y + (size_t)warp * DIM))[lane] = s;
    float2* ap = (float2*)(g_acc + (size_t)warp * DIM);
    float2 a = ap[lane];
    a.x += s.x; a.y += s.y;
    ap[lane] = a;
}

// -------- final gather + dot: one warp per (user,item) pair --------
__global__ void dot_kernel(const void* __restrict__ users, const void* __restrict__ items,
                           float* __restrict__ out, int B, int n_users) {
    const bool is64 = (g_is64 != 0);
    int warp = (blockIdx.x * blockDim.x + threadIdx.x) >> 5;
    int lane = threadIdx.x & 31;
    if (warp >= B) return;
    int u  = load_idx(users, warp, is64);
    int it = load_idx(items, warp, is64);
    const float2* up = (const float2*)(g_acc + (size_t)u * DIM);
    const float2* ip = (const float2*)(g_acc + ((size_t)n_users + it) * DIM);
    float2 a = up[lane];
    float2 b = ip[lane];
    float p = a.x * b.x + a.y * b.y;
    #pragma unroll
    for (int off = 16; off > 0; off >>= 1)
        p += __shfl_xor_sync(0xffffffffu, p, off);
    if (lane == 0) out[warp] = p * (1.0f / ((N_LAYERS + 1) * (N_LAYERS + 1)));
}

extern "C" void kernel_launch(void* const* d_in, const int* in_sizes, int n_in,
                              void* d_out, int out_size) {
    // ---- resolve input permutation from size fingerprint ----
    // dict order  : users(B) items(B) src(E) dst(E) vals(E) ue(NU*D) ie(NI*D)
    // alpha order : dst(E) src(E) vals(E) ie(NI*D) items(B) ue(NU*D) users(B)
    int iu, ii, is, id, iv, iue, iie;
    if ((long long)in_sizes[0] < (long long)in_sizes[2]) {
        iu = 0; ii = 1; is = 2; id = 3; iv = 4; iue = 5; iie = 6;   // dict order
    } else {
        id = 0; is = 1; iv = 2; iie = 3; ii = 4; iue = 5; iu = 6;   // alphabetical
    }
    const void*  users    = d_in[iu];
    const void*  items    = d_in[ii];
    const void*  edge_src = d_in[is];
    const void*  edge_dst = d_in[id];
    const float* edge_val = (const float*)d_in[iv];
    const float* user_emb = (const float*)d_in[iue];
    const float* item_emb = (const float*)d_in[iie];
    float* out = (float*)d_out;

    const int B       = in_sizes[iu];
    const int n_edges = in_sizes[is];
    const int n_users = in_sizes[iue] / DIM;
    const int n_items = in_sizes[iie] / DIM;
    const int n_nodes = n_users + n_items;
    const int nU4 = n_users * DIM / 4;
    const int nT4 = n_nodes * DIM / 4;

    // dtype detection + init + CSR build
    int nslots = n_edges / 2 < 4096 ? n_edges / 2 : 4096;
    detect_kernel<<<1, 1024>>>((const unsigned int*)edge_src, nslots);
    init_kernel<<<(nT4 + 255) / 256, 256>>>(user_emb, item_emb, nU4, nT4, n_nodes);
    hist_kernel<<<2048, 256>>>(edge_dst, n_edges);
    scan_kernel<<<1, 1024>>>(n_nodes);
    fill_kernel<<<2048, 256>>>(edge_src, edge_dst, edge_val, n_edges);

    // 3 propagation layers (ping-pong via device-side selector), acc fused
    int spmm_grid = (n_nodes * 32 + 255) / 256;
    spmm_kernel<<<spmm_grid, 256>>>(0, n_nodes);   // layer 1: A -> B
    spmm_kernel<<<spmm_grid, 256>>>(1, n_nodes);   // layer 2: B -> A
    spmm_kernel<<<spmm_grid, 256>>>(0, n_nodes);   // layer 3: A -> B

    // final dots
    dot_kernel<<<(B * 32 + 255) / 256, 256>>>(users, items, out, B, n_users);
}

// round 6
// speedup vs baseline: 1.2913x; 1.2913x over previous
#include <cuda_runtime.h>
#include <cuda_bf16.h>

#define DIM 64
#define N_LAYERS 3
#define NODES_MAX 262144
#define EDGES_MAX 16000000
#define SCAN_BLK 1024
#define PARTS_MAX 256   // NODES_MAX / SCAN_BLK

// -------- static device scratch (no allocations allowed) --------
// NOTE: referenced ONLY from device code (host-side symbol decay = ATS-backed
// host shadow on GB300 — the silent R2-R4 bug).
__device__ int   g_is64;                        // 1 if index inputs are int64
__device__ int   g_counts [NODES_MAX];          // counts, then local exclusive scan
__device__ int   g_part   [PARTS_MAX];          // per-block totals -> exclusive bases
__device__ int   g_offsets[NODES_MAX + 1];
__device__ int   g_cursor [NODES_MAX];
__device__ int2  g_csr    [EDGES_MAX];          // (src, val-bits) grouped by dst
__device__ float g_bufA   [NODES_MAX * DIM];
__device__ float g_bufB   [NODES_MAX * DIM];
__device__ float g_acc    [NODES_MAX * DIM];

// -------- index load helper: int32 or int64 input buffers --------
__device__ __forceinline__ int load_idx(const void* p, int i, bool is64) {
    if (is64) return (int)((const long long*)p)[i];
    return ((const int*)p)[i];
}

// -------- dtype detection: odd 32-bit words all zero => int64 --------
__global__ void detect_kernel(const unsigned int* __restrict__ p, int nslots) {
    __shared__ unsigned int acc;
    if (threadIdx.x == 0) acc = 0u;
    __syncthreads();
    unsigned int v = 0u;
    for (int s = threadIdx.x; s < nslots; s += 1024) v |= p[2 * s + 1];
    if (v) atomicOr(&acc, 1u);
    __syncthreads();
    if (threadIdx.x == 0) g_is64 = (acc == 0u) ? 1 : 0;
}

// -------- init: cur0 = concat(user_emb, item_emb); acc = cur0; counts = 0 ----
__global__ void init_kernel(const float* __restrict__ ue, const float* __restrict__ ie,
                            int nU4, int nT4, int n_nodes) {
    int i = blockIdx.x * blockDim.x + threadIdx.x;   // float4 index
    if (i < nT4) {
        float4 v = (i < nU4) ? ((const float4*)ue)[i] : ((const float4*)ie)[i - nU4];
        ((float4*)g_bufA)[i] = v;
        ((float4*)g_acc)[i]  = v;
    }
    if (i < n_nodes) g_counts[i] = 0;
}

// -------- histogram of destinations --------
__global__ void hist_kernel(const void* __restrict__ dst, int n_edges) {
    const bool is64 = (g_is64 != 0);
    int stride = gridDim.x * blockDim.x;
    for (int e = blockIdx.x * blockDim.x + threadIdx.x; e < n_edges; e += stride)
        atomicAdd(&g_counts[load_idx(dst, e, is64)], 1);
}

// ======== 3-phase parallel exclusive scan (replaces 244us single-block scan) =
// Phase 1: per-block exclusive scan of counts (in place) + block total.
__global__ void __launch_bounds__(SCAN_BLK)
scan_blocks_kernel(int n_nodes) {
    __shared__ int warp_tot[32];
    int tid  = threadIdx.x;
    int lane = tid & 31, wid = tid >> 5;
    int i = blockIdx.x * SCAN_BLK + tid;
    int v = (i < n_nodes) ? g_counts[i] : 0;

    int x = v;                                   // warp inclusive scan
    #pragma unroll
    for (int o = 1; o < 32; o <<= 1) {
        int t = __shfl_up_sync(0xffffffffu, x, o);
        if (lane >= o) x += t;
    }
    if (lane == 31) warp_tot[wid] = x;
    __syncthreads();
    if (wid == 0) {                              // scan the 32 warp totals
        int w = warp_tot[lane];
        #pragma unroll
        for (int o = 1; o < 32; o <<= 1) {
            int t = __shfl_up_sync(0xffffffffu, w, o);
            if (lane >= o) w += t;
        }
        warp_tot[lane] = w;
    }
    __syncthreads();
    int base = wid ? warp_tot[wid - 1] : 0;
    int incl = base + x;
    if (i < n_nodes) g_counts[i] = incl - v;     // exclusive-within-block (reuse)
    if (tid == SCAN_BLK - 1) g_part[blockIdx.x] = incl;   // block total
}

// Phase 2: single block scans <=256 block totals -> exclusive bases; writes grand total.
__global__ void __launch_bounds__(PARTS_MAX)
scan_parts_kernel(int nb, int n_nodes) {
    __shared__ int warp_tot[8];
    int tid = threadIdx.x, lane = tid & 31, wid = tid >> 5;
    int v = (tid < nb) ? g_part[tid] : 0;
    int x = v;
    #pragma unroll
    for (int o = 1; o < 32; o <<= 1) {
        int t = __shfl_up_sync(0xffffffffu, x, o);
        if (lane >= o) x += t;
    }
    if (lane == 31) warp_tot[wid] = x;
    __syncthreads();
    if (wid == 0 && lane < 8) {
        int w = warp_tot[lane];
        #pragma unroll
        for (int o = 1; o < 8; o <<= 1) {
            int t = __shfl_up_sync(0xffu, w, o);
            if (lane >= o) w += t;
        }
        warp_tot[lane] = w;
    }
    __syncthreads();
    int base = wid ? warp_tot[wid - 1] : 0;
    int incl = base + x;
    if (tid < nb) g_part[tid] = incl - v;        // exclusive base per block
    if (tid == PARTS_MAX - 1) g_offsets[n_nodes] = incl;  // grand total == n_edges
}

// Phase 3: add block base; emit offsets + cursor.
__global__ void __launch_bounds__(SCAN_BLK)
scan_add_kernel(int n_nodes) {
    int i = blockIdx.x * SCAN_BLK + threadIdx.x;
    if (i < n_nodes) {
        int o = g_counts[i] + g_part[blockIdx.x];
        g_offsets[i] = o;
        g_cursor [i] = o;
    }
}

// -------- scatter edges into CSR slots --------
__global__ void fill_kernel(const void* __restrict__ src, const void* __restrict__ dst,
                            const float* __restrict__ val, int n_edges) {
    const bool is64 = (g_is64 != 0);
    int stride = gridDim.x * blockDim.x;
    for (int e = blockIdx.x * blockDim.x + threadIdx.x; e < n_edges; e += stride) {
        int d = load_idx(dst, e, is64);
        int pos = atomicAdd(&g_cursor[d], 1);
        g_csr[pos] = make_int2(load_idx(src, e, is64), __float_as_int(val[e]));
    }
}

// -------- SpMM gather: one warp per dst node; lane owns a float2 of the row --
// sel=0: x=g_bufA, y=g_bufB.  sel=1: x=g_bufB, y=g_bufA.
__global__ void __launch_bounds__(256)
spmm_kernel(int sel, int n_nodes) {
    const float* __restrict__ x = sel ? g_bufB : g_bufA;
    float*       __restrict__ y = sel ? g_bufA : g_bufB;
    int warp = (blockIdx.x * blockDim.x + threadIdx.x) >> 5;
    int lane = threadIdx.x & 31;
    if (warp >= n_nodes) return;
    int beg = g_offsets[warp];
    int end = g_offsets[warp + 1];

    float2 s = make_float2(0.f, 0.f);
    int e = beg;
    for (; e + 32 <= end; e += 32) {
        int2 ev = g_csr[e + lane];
        #pragma unroll
        for (int k = 0; k < 32; k++) {
            int   sN = __shfl_sync(0xffffffffu, ev.x, k);
            float vN = __int_as_float(__shfl_sync(0xffffffffu, ev.y, k));
            float2 xf = *(const float2*)(x + (size_t)sN * DIM + lane * 2);
            s.x += vN * xf.x;
            s.y += vN * xf.y;
        }
    }
    int n = end - e;
    if (n > 0) {
        int2 ev = (lane < n) ? g_csr[e + lane] : make_int2(0, 0);
        for (int k = 0; k < n; k++) {
            int   sN = __shfl_sync(0xffffffffu, ev.x, k);
            float vN = __int_as_float(__shfl_sync(0xffffffffu, ev.y, k));
            float2 xf = *(const float2*)(x + (size_t)sN * DIM + lane * 2);
            s.x += vN * xf.x;
            s.y += vN * xf.y;
        }
    }

    ((float2*)(y + (size_t)warp * DIM))[lane] = s;
    float2* ap = (float2*)(g_acc + (size_t)warp * DIM);
    float2 a = ap[lane];
    a.x += s.x; a.y += s.y;
    ap[lane] = a;
}

// -------- final gather + dot: one warp per (user,item) pair --------
__global__ void dot_kernel(const void* __restrict__ users, const void* __restrict__ items,
                           float* __restrict__ out, int B, int n_users) {
    const bool is64 = (g_is64 != 0);
    int warp = (blockIdx.x * blockDim.x + threadIdx.x) >> 5;
    int lane = threadIdx.x & 31;
    if (warp >= B) return;
    int u  = load_idx(users, warp, is64);
    int it = load_idx(items, warp, is64);
    const float2* up = (const float2*)(g_acc + (size_t)u * DIM);
    const float2* ip = (const float2*)(g_acc + ((size_t)n_users + it) * DIM);
    float2 a = up[lane];
    float2 b = ip[lane];
    float p = a.x * b.x + a.y * b.y;
    #pragma unroll
    for (int off = 16; off > 0; off >>= 1)
        p += __shfl_xor_sync(0xffffffffu, p, off);
    if (lane == 0) out[warp] = p * (1.0f / ((N_LAYERS + 1) * (N_LAYERS + 1)));
}

extern "C" void kernel_launch(void* const* d_in, const int* in_sizes, int n_in,
                              void* d_out, int out_size) {
    // ---- resolve input permutation from size fingerprint ----
    // dict order  : users(B) items(B) src(E) dst(E) vals(E) ue(NU*D) ie(NI*D)
    // alpha order : dst(E) src(E) vals(E) ie(NI*D) items(B) ue(NU*D) users(B)
    int iu, ii, is, id, iv, iue, iie;
    if ((long long)in_sizes[0] < (long long)in_sizes[2]) {
        iu = 0; ii = 1; is = 2; id = 3; iv = 4; iue = 5; iie = 6;   // dict order
    } else {
        id = 0; is = 1; iv = 2; iie = 3; ii = 4; iue = 5; iu = 6;   // alphabetical
    }
    const void*  users    = d_in[iu];
    const void*  items    = d_in[ii];
    const void*  edge_src = d_in[is];
    const void*  edge_dst = d_in[id];
    const float* edge_val = (const float*)d_in[iv];
    const float* user_emb = (const float*)d_in[iue];
    const float* item_emb = (const float*)d_in[iie];
    float* out = (float*)d_out;

    const int B       = in_sizes[iu];
    const int n_edges = in_sizes[is];
    const int n_users = in_sizes[iue] / DIM;
    const int n_items = in_sizes[iie] / DIM;
    const int n_nodes = n_users + n_items;
    const int nU4 = n_users * DIM / 4;
    const int nT4 = n_nodes * DIM / 4;
    const int nb  = (n_nodes + SCAN_BLK - 1) / SCAN_BLK;   // <= PARTS_MAX

    // dtype detection + init + CSR build
    int nslots = n_edges / 2 < 4096 ? n_edges / 2 : 4096;
    detect_kernel<<<1, 1024>>>((const unsigned int*)edge_src, nslots);
    init_kernel<<<(nT4 + 255) / 256, 256>>>(user_emb, item_emb, nU4, nT4, n_nodes);
    hist_kernel<<<2048, 256>>>(edge_dst, n_edges);
    scan_blocks_kernel<<<nb, SCAN_BLK>>>(n_nodes);
    scan_parts_kernel<<<1, PARTS_MAX>>>(nb, n_nodes);
    scan_add_kernel<<<nb, SCAN_BLK>>>(n_nodes);
    fill_kernel<<<2048, 256>>>(edge_src, edge_dst, edge_val, n_edges);

    // 3 propagation layers (ping-pong via device-side selector), acc fused
    int spmm_grid = (n_nodes * 32 + 255) / 256;
    spmm_kernel<<<spmm_grid, 256>>>(0, n_nodes);   // layer 1: A -> B
    spmm_kernel<<<spmm_grid, 256>>>(1, n_nodes);   // layer 2: B -> A
    spmm_kernel<<<spmm_grid, 256>>>(0, n_nodes);   // layer 3: A -> B

    // final dots
    dot_kernel<<<(B * 32 + 255) / 256, 256>>>(users, items, out, B, n_users);
}

// round 7
// speedup vs baseline: 1.4594x; 1.1302x over previous
#include <cuda_runtime.h>
#include <cuda_fp16.h>

#define DIM 64
#define DIM2 (DIM / 2)
#define N_LAYERS 3
#define NODES_MAX 262144
#define EDGES_MAX 16000000
#define SCAN_BLK 1024
#define PARTS_MAX 256   // NODES_MAX / SCAN_BLK

// -------- static device scratch (no allocations allowed) --------
// Referenced ONLY from device code (host-side symbol decay = ATS-backed
// host shadow on GB300 — the silent R2-R4 bug).
__device__ int     g_is64;
__device__ int     g_counts [NODES_MAX];
__device__ int     g_part   [PARTS_MAX];
__device__ int     g_offsets[NODES_MAX + 1];
__device__ int     g_cursor [NODES_MAX];
__device__ int2    g_csr    [EDGES_MAX];           // (src, val-bits) grouped by dst
__device__ __half2 h_bufA   [NODES_MAX * DIM2];    // fp16 node features (ping)
__device__ __half2 h_bufB   [NODES_MAX * DIM2];    // fp16 node features (pong)
__device__ float   g_acc    [NODES_MAX * DIM];     // fp32 accumulator

// -------- index load helper: int32 or int64 input buffers --------
__device__ __forceinline__ int load_idx(const void* p, int i, bool is64) {
    if (is64) return (int)((const long long*)p)[i];
    return ((const int*)p)[i];
}

// -------- dtype detection: odd 32-bit words all zero => int64 --------
__global__ void detect_kernel(const unsigned int* __restrict__ p, int nslots) {
    __shared__ unsigned int acc;
    if (threadIdx.x == 0) acc = 0u;
    __syncthreads();
    unsigned int v = 0u;
    for (int s = threadIdx.x; s < nslots; s += 1024) v |= p[2 * s + 1];
    if (v) atomicOr(&acc, 1u);
    __syncthreads();
    if (threadIdx.x == 0) g_is64 = (acc == 0u) ? 1 : 0;
}

// -------- init: h_bufA = fp16(emb); g_acc = fp32(emb); counts = 0 --------
__global__ void init_kernel(const float* __restrict__ ue, const float* __restrict__ ie,
                            int nU2, int nT2, int n_nodes) {
    int i = blockIdx.x * blockDim.x + threadIdx.x;   // float2 index
    if (i < nT2) {
        float2 v = (i < nU2) ? ((const float2*)ue)[i] : ((const float2*)ie)[i - nU2];
        h_bufA[i] = __floats2half2_rn(v.x, v.y);
        ((float2*)g_acc)[i] = v;
    }
    if (i < n_nodes) g_counts[i] = 0;
}

// -------- histogram of destinations --------
__global__ void hist_kernel(const void* __restrict__ dst, int n_edges) {
    const bool is64 = (g_is64 != 0);
    int stride = gridDim.x * blockDim.x;
    for (int e = blockIdx.x * blockDim.x + threadIdx.x; e < n_edges; e += stride)
        atomicAdd(&g_counts[load_idx(dst, e, is64)], 1);
}

// ======== 3-phase parallel exclusive scan ========
__global__ void __launch_bounds__(SCAN_BLK)
scan_blocks_kernel(int n_nodes) {
    __shared__ int warp_tot[32];
    int tid  = threadIdx.x;
    int lane = tid & 31, wid = tid >> 5;
    int i = blockIdx.x * SCAN_BLK + tid;
    int v = (i < n_nodes) ? g_counts[i] : 0;

    int x = v;
    #pragma unroll
    for (int o = 1; o < 32; o <<= 1) {
        int t = __shfl_up_sync(0xffffffffu, x, o);
        if (lane >= o) x += t;
    }
    if (lane == 31) warp_tot[wid] = x;
    __syncthreads();
    if (wid == 0) {
        int w = warp_tot[lane];
        #pragma unroll
        for (int o = 1; o < 32; o <<= 1) {
            int t = __shfl_up_sync(0xffffffffu, w, o);
            if (lane >= o) w += t;
        }
        warp_tot[lane] = w;
    }
    __syncthreads();
    int base = wid ? warp_tot[wid - 1] : 0;
    int incl = base + x;
    if (i < n_nodes) g_counts[i] = incl - v;
    if (tid == SCAN_BLK - 1) g_part[blockIdx.x] = incl;
}

__global__ void __launch_bounds__(PARTS_MAX)
scan_parts_kernel(int nb, int n_nodes) {
    __shared__ int warp_tot[8];
    int tid = threadIdx.x, lane = tid & 31, wid = tid >> 5;
    int v = (tid < nb) ? g_part[tid] : 0;
    int x = v;
    #pragma unroll
    for (int o = 1; o < 32; o <<= 1) {
        int t = __shfl_up_sync(0xffffffffu, x, o);
        if (lane >= o) x += t;
    }
    if (lane == 31) warp_tot[wid] = x;
    __syncthreads();
    if (wid == 0 && lane < 8) {
        int w = warp_tot[lane];
        #pragma unroll
        for (int o = 1; o < 8; o <<= 1) {
            int t = __shfl_up_sync(0xffu, w, o);
            if (lane >= o) w += t;
        }
        warp_tot[lane] = w;
    }
    __syncthreads();
    int base = wid ? warp_tot[wid - 1] : 0;
    int incl = base + x;
    if (tid < nb) g_part[tid] = incl - v;
    if (tid == PARTS_MAX - 1) g_offsets[n_nodes] = incl;
}

__global__ void __launch_bounds__(SCAN_BLK)
scan_add_kernel(int n_nodes) {
    int i = blockIdx.x * SCAN_BLK + threadIdx.x;
    if (i < n_nodes) {
        int o = g_counts[i] + g_part[blockIdx.x];
        g_offsets[i] = o;
        g_cursor [i] = o;
    }
}

// -------- scatter edges into CSR slots --------
__global__ void fill_kernel(const void* __restrict__ src, const void* __restrict__ dst,
                            const float* __restrict__ val, int n_edges) {
    const bool is64 = (g_is64 != 0);
    int stride = gridDim.x * blockDim.x;
    for (int e = blockIdx.x * blockDim.x + threadIdx.x; e < n_edges; e += stride) {
        int d = load_idx(dst, e, is64);
        int pos = atomicAdd(&g_cursor[d], 1);
        g_csr[pos] = make_int2(load_idx(src, e, is64), __float_as_int(val[e]));
    }
}

// -------- SpMM gather: fp16 rows (128B/row), fp32 math + fp32 acc --------
// sel=0: x=h_bufA, y=h_bufB.  sel=1: x=h_bufB, y=h_bufA.
// write_y=0 on the last layer (y unused).
__global__ void __launch_bounds__(256)
spmm_kernel(int sel, int write_y, int n_nodes) {
    const __half2* __restrict__ x = sel ? h_bufB : h_bufA;
    __half2*       __restrict__ y = sel ? h_bufA : h_bufB;
    int warp = (blockIdx.x * blockDim.x + threadIdx.x) >> 5;
    int lane = threadIdx.x & 31;
    if (warp >= n_nodes) return;
    int beg = g_offsets[warp];
    int end = g_offsets[warp + 1];

    float2 s = make_float2(0.f, 0.f);
    int e = beg;
    for (; e + 32 <= end; e += 32) {
        int2 ev = g_csr[e + lane];
        #pragma unroll
        for (int k = 0; k < 32; k++) {
            int   sN = __shfl_sync(0xffffffffu, ev.x, k);
            float vN = __int_as_float(__shfl_sync(0xffffffffu, ev.y, k));
            float2 xf = __half22float2(x[sN * DIM2 + lane]);
            s.x += vN * xf.x;
            s.y += vN * xf.y;
        }
    }
    int n = end - e;
    if (n > 0) {
        int2 ev = (lane < n) ? g_csr[e + lane] : make_int2(0, 0);
        for (int k = 0; k < n; k++) {
            int   sN = __shfl_sync(0xffffffffu, ev.x, k);
            float vN = __int_as_float(__shfl_sync(0xffffffffu, ev.y, k));
            float2 xf = __half22float2(x[sN * DIM2 + lane]);
            s.x += vN * xf.x;
            s.y += vN * xf.y;
        }
    }

    if (write_y) y[(size_t)warp * DIM2 + lane] = __floats2half2_rn(s.x, s.y);
    float2* ap = (float2*)(g_acc + (size_t)warp * DIM);
    float2 a = ap[lane];
    a.x += s.x; a.y += s.y;
    ap[lane] = a;
}

// -------- final gather + dot (fp32 acc): one warp per (user,item) pair -------
__global__ void dot_kernel(const void* __restrict__ users, const void* __restrict__ items,
                           float* __restrict__ out, int B, int n_users) {
    const bool is64 = (g_is64 != 0);
    int warp = (blockIdx.x * blockDim.x + threadIdx.x) >> 5;
    int lane = threadIdx.x & 31;
    if (warp >= B) return;
    int u  = load_idx(users, warp, is64);
    int it = load_idx(items, warp, is64);
    const float2* up = (const float2*)(g_acc + (size_t)u * DIM);
    const float2* ip = (const float2*)(g_acc + ((size_t)n_users + it) * DIM);
    float2 a = up[lane];
    float2 b = ip[lane];
    float p = a.x * b.x + a.y * b.y;
    #pragma unroll
    for (int off = 16; off > 0; off >>= 1)
        p += __shfl_xor_sync(0xffffffffu, p, off);
    if (lane == 0) out[warp] = p * (1.0f / ((N_LAYERS + 1) * (N_LAYERS + 1)));
}

extern "C" void kernel_launch(void* const* d_in, const int* in_sizes, int n_in,
                              void* d_out, int out_size) {
    // ---- resolve input permutation from size fingerprint ----
    // dict order  : users(B) items(B) src(E) dst(E) vals(E) ue(NU*D) ie(NI*D)
    // alpha order : dst(E) src(E) vals(E) ie(NI*D) items(B) ue(NU*D) users(B)
    int iu, ii, is, id, iv, iue, iie;
    if ((long long)in_sizes[0] < (long long)in_sizes[2]) {
        iu = 0; ii = 1; is = 2; id = 3; iv = 4; iue = 5; iie = 6;   // dict order
    } else {
        id = 0; is = 1; iv = 2; iie = 3; ii = 4; iue = 5; iu = 6;   // alphabetical
    }
    const void*  users    = d_in[iu];
    const void*  items    = d_in[ii];
    const void*  edge_src = d_in[is];
    const void*  edge_dst = d_in[id];
    const float* edge_val = (const float*)d_in[iv];
    const float* user_emb = (const float*)d_in[iue];
    const float* item_emb = (const float*)d_in[iie];
    float* out = (float*)d_out;

    const int B       = in_sizes[iu];
    const int n_edges = in_sizes[is];
    const int n_users = in_sizes[iue] / DIM;
    const int n_items = in_sizes[iie] / DIM;
    const int n_nodes = n_users + n_items;
    const int nU2 = n_users * DIM / 2;
    const int nT2 = n_nodes * DIM / 2;
    const int nb  = (n_nodes + SCAN_BLK - 1) / SCAN_BLK;   // <= PARTS_MAX

    // dtype detection + init + CSR build
    int nslots = n_edges / 2 < 4096 ? n_edges / 2 : 4096;
    detect_kernel<<<1, 1024>>>((const unsigned int*)edge_src, nslots);
    init_kernel<<<(nT2 + 255) / 256, 256>>>(user_emb, item_emb, nU2, nT2, n_nodes);
    hist_kernel<<<2048, 256>>>(edge_dst, n_edges);
    scan_blocks_kernel<<<nb, SCAN_BLK>>>(n_nodes);
    scan_parts_kernel<<<1, PARTS_MAX>>>(nb, n_nodes);
    scan_add_kernel<<<nb, SCAN_BLK>>>(n_nodes);
    fill_kernel<<<2048, 256>>>(edge_src, edge_dst, edge_val, n_edges);

    // 3 propagation layers (ping-pong via device-side selector), acc fused
    int spmm_grid = (n_nodes * 32 + 255) / 256;
    spmm_kernel<<<spmm_grid, 256>>>(0, 1, n_nodes);   // layer 1: A -> B
    spmm_kernel<<<spmm_grid, 256>>>(1, 1, n_nodes);   // layer 2: B -> A
    spmm_kernel<<<spmm_grid, 256>>>(0, 0, n_nodes);   // layer 3: A -> (acc only)

    // final dots
    dot_kernel<<<(B * 32 + 255) / 256, 256>>>(users, items, out, B, n_users);
}

// round 8
// speedup vs baseline: 1.7292x; 1.1849x over previous
#include <cuda_runtime.h>
#include <cuda_fp16.h>

#define DIM 64
#define DIM2 (DIM / 2)
#define N_LAYERS 3
#define NODES_MAX 262144
#define EDGES_MAX 16000000
#define SCAN_BLK 1024
#define PARTS_MAX 256   // NODES_MAX / SCAN_BLK

// -------- static device scratch (no allocations allowed) --------
// Referenced ONLY from device code (host-side symbol decay = ATS-backed
// host shadow on GB300 — the silent R2-R4 bug).
__device__ int     g_is64;
__device__ int     g_counts [NODES_MAX];
__device__ int     g_part   [PARTS_MAX];
__device__ int     g_offsets[NODES_MAX + 1];
__device__ int     g_cursor [NODES_MAX];
__device__ int     g_flag   [NODES_MAX];          // 1 if node is queried by dot
__device__ int2    g_csr    [EDGES_MAX];          // (src, val-bits) grouped by dst
__device__ __half2 h_bufA   [NODES_MAX * DIM2];   // e0 -> later layer-2 output
__device__ __half2 h_bufB   [NODES_MAX * DIM2];   // layer-1 output
__device__ float   g_l3     [NODES_MAX * DIM];    // layer-3 output (flagged rows only)

// -------- index load helper: int32 or int64 input buffers --------
__device__ __forceinline__ int load_idx(const void* p, int i, bool is64) {
    if (is64) return (int)((const long long*)p)[i];
    return ((const int*)p)[i];
}

// -------- dtype detection: odd 32-bit words all zero => int64 --------
__global__ void detect_kernel(const unsigned int* __restrict__ p, int nslots) {
    __shared__ unsigned int acc;
    if (threadIdx.x == 0) acc = 0u;
    __syncthreads();
    unsigned int v = 0u;
    for (int s = threadIdx.x; s < nslots; s += 1024) v |= p[2 * s + 1];
    if (v) atomicOr(&acc, 1u);
    __syncthreads();
    if (threadIdx.x == 0) g_is64 = (acc == 0u) ? 1 : 0;
}

// -------- init: h_bufA = fp16(emb); counts = flag = 0 --------
__global__ void init_kernel(const float* __restrict__ ue, const float* __restrict__ ie,
                            int nU2, int nT2, int n_nodes) {
    int i = blockIdx.x * blockDim.x + threadIdx.x;   // float2 index
    if (i < nT2) {
        float2 v = (i < nU2) ? ((const float2*)ue)[i] : ((const float2*)ie)[i - nU2];
        h_bufA[i] = __floats2half2_rn(v.x, v.y);
    }
    if (i < n_nodes) { g_counts[i] = 0; g_flag[i] = 0; }
}

// -------- flag queried nodes (benign races: plain store of 1) --------
__global__ void flag_kernel(const void* __restrict__ users, const void* __restrict__ items,
                            int B, int n_users) {
    const bool is64 = (g_is64 != 0);
    int i = blockIdx.x * blockDim.x + threadIdx.x;
    if (i < B) {
        g_flag[load_idx(users, i, is64)] = 1;
        g_flag[n_users + load_idx(items, i, is64)] = 1;
    }
}

// -------- histogram of destinations --------
__global__ void hist_kernel(const void* __restrict__ dst, int n_edges) {
    const bool is64 = (g_is64 != 0);
    int stride = gridDim.x * blockDim.x;
    for (int e = blockIdx.x * blockDim.x + threadIdx.x; e < n_edges; e += stride)
        atomicAdd(&g_counts[load_idx(dst, e, is64)], 1);
}

// ======== 3-phase parallel exclusive scan ========
__global__ void __launch_bounds__(SCAN_BLK)
scan_blocks_kernel(int n_nodes) {
    __shared__ int warp_tot[32];
    int tid  = threadIdx.x;
    int lane = tid & 31, wid = tid >> 5;
    int i = blockIdx.x * SCAN_BLK + tid;
    int v = (i < n_nodes) ? g_counts[i] : 0;

    int x = v;
    #pragma unroll
    for (int o = 1; o < 32; o <<= 1) {
        int t = __shfl_up_sync(0xffffffffu, x, o);
        if (lane >= o) x += t;
    }
    if (lane == 31) warp_tot[wid] = x;
    __syncthreads();
    if (wid == 0) {
        int w = warp_tot[lane];
        #pragma unroll
        for (int o = 1; o < 32; o <<= 1) {
            int t = __shfl_up_sync(0xffffffffu, w, o);
            if (lane >= o) w += t;
        }
        warp_tot[lane] = w;
    }
    __syncthreads();
    int base = wid ? warp_tot[wid - 1] : 0;
    int incl = base + x;
    if (i < n_nodes) g_counts[i] = incl - v;
    if (tid == SCAN_BLK - 1) g_part[blockIdx.x] = incl;
}

__global__ void __launch_bounds__(PARTS_MAX)
scan_parts_kernel(int nb, int n_nodes) {
    __shared__ int warp_tot[8];
    int tid = threadIdx.x, lane = tid & 31, wid = tid >> 5;
    int v = (tid < nb) ? g_part[tid] : 0;
    int x = v;
    #pragma unroll
    for (int o = 1; o < 32; o <<= 1) {
        int t = __shfl_up_sync(0xffffffffu, x, o);
        if (lane >= o) x += t;
    }
    if (lane == 31) warp_tot[wid] = x;
    __syncthreads();
    if (wid == 0 && lane < 8) {
        int w = warp_tot[lane];
        #pragma unroll
        for (int o = 1; o < 8; o <<= 1) {
            int t = __shfl_up_sync(0xffu, w, o);
            if (lane >= o) w += t;
        }
        warp_tot[lane] = w;
    }
    __syncthreads();
    int base = wid ? warp_tot[wid - 1] : 0;
    int incl = base + x;
    if (tid < nb) g_part[tid] = incl - v;
    if (tid == PARTS_MAX - 1) g_offsets[n_nodes] = incl;
}

__global__ void __launch_bounds__(SCAN_BLK)
scan_add_kernel(int n_nodes) {
    int i = blockIdx.x * SCAN_BLK + threadIdx.x;
    if (i < n_nodes) {
        int o = g_counts[i] + g_part[blockIdx.x];
        g_offsets[i] = o;
        g_cursor [i] = o;
    }
}

// -------- scatter edges into CSR slots --------
__global__ void fill_kernel(const void* __restrict__ src, const void* __restrict__ dst,
                            const float* __restrict__ val, int n_edges) {
    const bool is64 = (g_is64 != 0);
    int stride = gridDim.x * blockDim.x;
    for (int e = blockIdx.x * blockDim.x + threadIdx.x; e < n_edges; e += stride) {
        int d = load_idx(dst, e, is64);
        int pos = atomicAdd(&g_cursor[d], 1);
        g_csr[pos] = make_int2(load_idx(src, e, is64), __float_as_int(val[e]));
    }
}

// -------- SpMM body: gather fp16 rows, fp32 math, dual accumulator chains ----
__device__ __forceinline__ float2 spmm_row(const __half2* __restrict__ x,
                                           int beg, int end, int lane) {
    float2 s0 = make_float2(0.f, 0.f), s1 = make_float2(0.f, 0.f);
    int e = beg;
    for (; e + 32 <= end; e += 32) {
        int2 ev = g_csr[e + lane];
        #pragma unroll
        for (int k = 0; k < 32; k += 2) {
            int   sA = __shfl_sync(0xffffffffu, ev.x, k);
            float vA = __int_as_float(__shfl_sync(0xffffffffu, ev.y, k));
            int   sB = __shfl_sync(0xffffffffu, ev.x, k + 1);
            float vB = __int_as_float(__shfl_sync(0xffffffffu, ev.y, k + 1));
            float2 xa = __half22float2(x[sA * DIM2 + lane]);
            float2 xb = __half22float2(x[sB * DIM2 + lane]);
            s0.x += vA * xa.x; s0.y += vA * xa.y;
            s1.x += vB * xb.x; s1.y += vB * xb.y;
        }
    }
    int n = end - e;
    if (n > 0) {
        int2 ev = (lane < n) ? g_csr[e + lane] : make_int2(0, 0);
        for (int k = 0; k < n; k++) {
            int   sN = __shfl_sync(0xffffffffu, ev.x, k);
            float vN = __int_as_float(__shfl_sync(0xffffffffu, ev.y, k));
            float2 xf = __half22float2(x[sN * DIM2 + lane]);
            if (k & 1) { s1.x += vN * xf.x; s1.y += vN * xf.y; }
            else       { s0.x += vN * xf.x; s0.y += vN * xf.y; }
        }
    }
    return make_float2(s0.x + s1.x, s0.y + s1.y);
}

// Layers 1-2: full graph, fp16 -> fp16. sel=0: A->B, sel=1: B->A.
__global__ void __launch_bounds__(256)
spmm_full_kernel(int sel, int n_nodes) {
    const __half2* __restrict__ x = sel ? h_bufB : h_bufA;
    __half2*       __restrict__ y = sel ? h_bufA : h_bufB;
    int warp = (blockIdx.x * blockDim.x + threadIdx.x) >> 5;
    int lane = threadIdx.x & 31;
    if (warp >= n_nodes) return;
    float2 s = spmm_row(x, g_offsets[warp], g_offsets[warp + 1], lane);
    y[(size_t)warp * DIM2 + lane] = __floats2half2_rn(s.x, s.y);
}

// Layer 3: flagged (queried) nodes only, fp16 -> fp32 g_l3.
__global__ void __launch_bounds__(256)
spmm_last_kernel(int n_nodes) {
    int warp = (blockIdx.x * blockDim.x + threadIdx.x) >> 5;
    int lane = threadIdx.x & 31;
    if (warp >= n_nodes) return;
    if (!g_flag[warp]) return;
    float2 s = spmm_row(h_bufA, g_offsets[warp], g_offsets[warp + 1], lane);
    ((float2*)(g_l3 + (size_t)warp * DIM))[lane] = s;
}

// -------- final dot: acc = e0(inputs) + l1(bufB) + l2(bufA) + l3(g_l3) -------
__global__ void dot_kernel(const void* __restrict__ users, const void* __restrict__ items,
                           const float* __restrict__ ue, const float* __restrict__ ie,
                           float* __restrict__ out, int B, int n_users) {
    const bool is64 = (g_is64 != 0);
    int warp = (blockIdx.x * blockDim.x + threadIdx.x) >> 5;
    int lane = threadIdx.x & 31;
    if (warp >= B) return;
    int u  = load_idx(users, warp, is64);
    int ni = n_users + load_idx(items, warp, is64);

    float2 e0u = ((const float2*)ue)[(size_t)u * DIM2 + lane];
    float2 l1u = __half22float2(h_bufB[(size_t)u * DIM2 + lane]);
    float2 l2u = __half22float2(h_bufA[(size_t)u * DIM2 + lane]);
    float2 l3u = ((const float2*)(g_l3 + (size_t)u * DIM))[lane];
    float ax = e0u.x + l1u.x + l2u.x + l3u.x;
    float ay = e0u.y + l1u.y + l2u.y + l3u.y;

    float2 e0i = ((const float2*)ie)[(size_t)(ni - n_users) * DIM2 + lane];
    float2 l1i = __half22float2(h_bufB[(size_t)ni * DIM2 + lane]);
    float2 l2i = __half22float2(h_bufA[(size_t)ni * DIM2 + lane]);
    float2 l3i = ((const float2*)(g_l3 + (size_t)ni * DIM))[lane];
    float bx = e0i.x + l1i.x + l2i.x + l3i.x;
    float by = e0i.y + l1i.y + l2i.y + l3i.y;

    float p = ax * bx + ay * by;
    #pragma unroll
    for (int off = 16; off > 0; off >>= 1)
        p += __shfl_xor_sync(0xffffffffu, p, off);
    if (lane == 0) out[warp] = p * (1.0f / ((N_LAYERS + 1) * (N_LAYERS + 1)));
}

extern "C" void kernel_launch(void* const* d_in, const int* in_sizes, int n_in,
                              void* d_out, int out_size) {
    // ---- resolve input permutation from size fingerprint ----
    int iu, ii, is, id, iv, iue, iie;
    if ((long long)in_sizes[0] < (long long)in_sizes[2]) {
        iu = 0; ii = 1; is = 2; id = 3; iv = 4; iue = 5; iie = 6;   // dict order
    } else {
        id = 0; is = 1; iv = 2; iie = 3; ii = 4; iue = 5; iu = 6;   // alphabetical
    }
    const void*  users    = d_in[iu];
    const void*  items    = d_in[ii];
    const void*  edge_src = d_in[is];
    const void*  edge_dst = d_in[id];
    const float* edge_val = (const float*)d_in[iv];
    const float* user_emb = (const float*)d_in[iue];
    const float* item_emb = (const float*)d_in[iie];
    float* out = (float*)d_out;

    const int B       = in_sizes[iu];
    const int n_edges = in_sizes[is];
    const int n_users = in_sizes[iue] / DIM;
    const int n_items = in_sizes[iie] / DIM;
    const int n_nodes = n_users + n_items;
    const int nU2 = n_users * DIM / 2;
    const int nT2 = n_nodes * DIM / 2;
    const int nb  = (n_nodes + SCAN_BLK - 1) / SCAN_BLK;   // <= PARTS_MAX

    // dtype detection + init + flags + CSR build
    int nslots = n_edges / 2 < 4096 ? n_edges / 2 : 4096;
    detect_kernel<<<1, 1024>>>((const unsigned int*)edge_src, nslots);
    init_kernel<<<(nT2 + 255) / 256, 256>>>(user_emb, item_emb, nU2, nT2, n_nodes);
    flag_kernel<<<(B + 255) / 256, 256>>>(users, items, B, n_users);
    hist_kernel<<<2048, 256>>>(edge_dst, n_edges);
    scan_blocks_kernel<<<nb, SCAN_BLK>>>(n_nodes);
    scan_parts_kernel<<<1, PARTS_MAX>>>(nb, n_nodes);
    scan_add_kernel<<<nb, SCAN_BLK>>>(n_nodes);
    fill_kernel<<<2048, 256>>>(edge_src, edge_dst, edge_val, n_edges);

    // propagation: layers 1-2 full, layer 3 only queried nodes
    int spmm_grid = (n_nodes * 32 + 255) / 256;
    spmm_full_kernel<<<spmm_grid, 256>>>(0, n_nodes);   // l1: A -> B
    spmm_full_kernel<<<spmm_grid, 256>>>(1, n_nodes);   // l2: B -> A
    spmm_last_kernel<<<spmm_grid, 256>>>(n_nodes);      // l3: A -> g_l3 (flagged)

    // final dots (acc assembled in-kernel)
    dot_kernel<<<(B * 32 + 255) / 256, 256>>>(users, items, user_emb, item_emb,
                                              out, B, n_users);
}